// round 14
// baseline (speedup 1.0000x reference)
#include <cuda_runtime.h>
#include <cuda_fp16.h>
#include <math.h>
#include <stdint.h>

#define B_ 8
#define C_ 512
#define L_ 2048
#define D_ 64

// Scratch (allocation-free rule: device globals)
__device__ float  g_q[B_*D_*L_];                 // (b, d, l)
__device__ float  g_k[B_*D_*L_];                 // (b, d, l)
__device__ __half g_v16[(size_t)B_*C_*L_];       // (b, c, l) fp16
__device__ __half g_a16[(size_t)B_*L_*L_];       // (b, m, l) fp16 attention copy

__device__ __forceinline__ uint32_t f2tf32(float f) {
    uint32_t u;
    asm("cvt.rna.tf32.f32 %0, %1;" : "=r"(u) : "f"(f));
    return u;
}
__device__ __forceinline__ uint32_t smem_u32(const void* p) {
    uint32_t a;
    asm("{ .reg .u64 t; cvta.to.shared.u64 t, %1; cvt.u32.u64 %0, t; }"
        : "=r"(a) : "l"(p));
    return a;
}
__device__ __forceinline__ void cp_async16(uint32_t dst, const void* src) {
    asm volatile("cp.async.ca.shared.global [%0], [%1], 16;"
                 :: "r"(dst), "l"(src));
}
#define CP_COMMIT() asm volatile("cp.async.commit_group;" ::: "memory")
#define CP_WAIT1()  asm volatile("cp.async.wait_group 1;" ::: "memory")
#define CP_WAIT0()  asm volatile("cp.async.wait_group 0;" ::: "memory")

#define MMA_TF32(acc, af, bf)                                                  \
    asm volatile(                                                              \
        "mma.sync.aligned.m16n8k8.row.col.f32.tf32.tf32.f32 "                  \
        "{%0,%1,%2,%3}, {%4,%5,%6,%7}, {%8,%9}, {%0,%1,%2,%3};"                \
        : "+f"((acc)[0]), "+f"((acc)[1]), "+f"((acc)[2]), "+f"((acc)[3])       \
        : "r"((af)[0]), "r"((af)[1]), "r"((af)[2]), "r"((af)[3]),              \
          "r"((bf)[0]), "r"((bf)[1]))

#define MMA_F16(acc, af, bf)                                                   \
    asm volatile(                                                              \
        "mma.sync.aligned.m16n8k16.row.col.f32.f16.f16.f32 "                   \
        "{%0,%1,%2,%3}, {%4,%5,%6,%7}, {%8,%9}, {%0,%1,%2,%3};"                \
        : "+f"((acc)[0]), "+f"((acc)[1]), "+f"((acc)[2]), "+f"((acc)[3])       \
        : "r"((af)[0]), "r"((af)[1]), "r"((af)[2]), "r"((af)[3]),              \
          "r"((bf)[0]), "r"((bf)[1]))

#define LDSM_X4(r0, r1, r2, r3, addr)                                          \
    asm volatile("ldmatrix.sync.aligned.m8n8.x4.shared.b16 {%0,%1,%2,%3}, [%4];" \
                 : "=r"(r0), "=r"(r1), "=r"(r2), "=r"(r3) : "r"(addr))

// ===========================================================================
// Kernel 1: q/k projection, 3xTF32 hi/lo, 64-wide l tiles (proven R9).
// ===========================================================================
#define QK_STAGE_F 6912
#define QK_SMEM_BYTES (2 * QK_STAGE_F * 4)   // 55296

__global__ __launch_bounds__(256, 2) void qk_proj_mma_kernel(
    const float* __restrict__ x,
    const float* __restrict__ Wq, const float* __restrict__ bq,
    const float* __restrict__ Wk, const float* __restrict__ bk)
{
    extern __shared__ __align__(16) float sm[];

    const int b  = blockIdx.z;
    const int l0 = blockIdx.x * 64;
    const int tid  = threadIdx.x;
    const int warp = tid >> 5;
    const int lane = tid & 31;
    const int warp_m = (warp & 3) * 32;
    const int warp_n = (warp >> 2) * 32;
    const int r  = lane >> 2;
    const int c4 = lane & 3;
    const uint32_t sbase = smem_u32(sm);

    const float* xb = x + (size_t)b * C_ * L_;

    const int rowL = tid >> 3;            // 0..31
    const int q8   = tid & 7;

    float acc[2][4][4] = {};

    auto load_slab = [&](int s) {
        const int st = s & 1;
        const int kc = s * 32;
        const uint32_t aoff = sbase + (uint32_t)(st * QK_STAGE_F) * 4u;
        const uint32_t boff = aoff + 4608u * 4u;
        #pragma unroll
        for (int i = 0; i < 4; i++) {
            const int rr = rowL + i * 32;
            const float* wp = (rr < 64) ? Wq + (size_t)rr * C_
                                        : Wk + (size_t)(rr - 64) * C_;
            cp_async16(aoff + ((uint32_t)rr * 36u + q8 * 4u) * 4u, wp + kc + q8 * 4);
        }
        #pragma unroll
        for (int i = 0; i < 2; i++) {
            const int f  = tid + i * 256;
            const int d  = f >> 4;        // 0..31
            const int l4 = f & 15;
            cp_async16(boff + ((uint32_t)d * 72u + l4 * 4u) * 4u,
                       xb + (size_t)(kc + d) * L_ + l0 + l4 * 4);
        }
        CP_COMMIT();
    };

    const int nst = C_ / 32;   // 16
    load_slab(0);

    for (int s = 0; s < nst; s++) {
        if (s + 1 < nst) { load_slab(s + 1); CP_WAIT1(); }
        else             { CP_WAIT0(); }
        __syncthreads();

        const float* As = sm + (s & 1) * QK_STAGE_F;
        const float* Bs = As + 4608;

        #pragma unroll
        for (int ks = 0; ks < 4; ks++) {
            const int k8 = ks * 8;
            uint32_t afh[2][4], afl[2][4], bfh[4][2], bfl[4][2];
            #pragma unroll
            for (int mt = 0; mt < 2; mt++) {
                const int ar = warp_m + mt * 16 + r;
                const float v0 = As[(ar    ) * 36 + k8 + c4];
                const float v1 = As[(ar + 8) * 36 + k8 + c4];
                const float v2 = As[(ar    ) * 36 + k8 + c4 + 4];
                const float v3 = As[(ar + 8) * 36 + k8 + c4 + 4];
                afh[mt][0] = f2tf32(v0); afl[mt][0] = f2tf32(v0 - __uint_as_float(afh[mt][0]));
                afh[mt][1] = f2tf32(v1); afl[mt][1] = f2tf32(v1 - __uint_as_float(afh[mt][1]));
                afh[mt][2] = f2tf32(v2); afl[mt][2] = f2tf32(v2 - __uint_as_float(afh[mt][2]));
                afh[mt][3] = f2tf32(v3); afl[mt][3] = f2tf32(v3 - __uint_as_float(afh[mt][3]));
            }
            #pragma unroll
            for (int nt = 0; nt < 4; nt++) {
                const int bn = warp_n + nt * 8 + r;
                const float w0 = Bs[(k8 + c4    ) * 72 + bn];
                const float w1 = Bs[(k8 + c4 + 4) * 72 + bn];
                bfh[nt][0] = f2tf32(w0); bfl[nt][0] = f2tf32(w0 - __uint_as_float(bfh[nt][0]));
                bfh[nt][1] = f2tf32(w1); bfl[nt][1] = f2tf32(w1 - __uint_as_float(bfh[nt][1]));
            }
            #pragma unroll
            for (int mt = 0; mt < 2; mt++)
                #pragma unroll
                for (int nt = 0; nt < 4; nt++) {
                    MMA_TF32(acc[mt][nt], afh[mt], bfh[nt]);
                    MMA_TF32(acc[mt][nt], afh[mt], bfl[nt]);
                    MMA_TF32(acc[mt][nt], afl[mt], bfh[nt]);
                }
        }
        __syncthreads();
    }

    #pragma unroll
    for (int mt = 0; mt < 2; mt++) {
        #pragma unroll
        for (int half = 0; half < 2; half++) {
            const int rr = warp_m + mt * 16 + r + half * 8;
            float bias; float* dst;
            if (rr < 64) { bias = bq[rr];    dst = g_q + ((size_t)b*D_ + rr)      * L_; }
            else         { bias = bk[rr-64]; dst = g_k + ((size_t)b*D_ + (rr-64)) * L_; }
            #pragma unroll
            for (int nt = 0; nt < 4; nt++) {
                const int col = l0 + warp_n + nt * 8 + c4 * 2;
                float2 o;
                o.x = acc[mt][nt][half*2 + 0] + bias;
                o.y = acc[mt][nt][half*2 + 1] + bias;
                *(float2*)(dst + col) = o;
            }
        }
    }
}

// ===========================================================================
// Kernel 2: FUSED energy + v-projection (proven R11).
// ===========================================================================
#define EN_STAGE_F 8704
#define QKV_STAGE_F 8960
#define EV_SMEM_BYTES (2 * QKV_STAGE_F * 4)   // 71680

__global__ __launch_bounds__(256, 2) void energy_v_fused_kernel(
    float* __restrict__ att,
    const float* __restrict__ x,
    const float* __restrict__ Wv, const float* __restrict__ bv)
{
    extern __shared__ __align__(16) float sm[];

    const int b   = blockIdx.z;
    const int yt  = blockIdx.y;
    const int tid = threadIdx.x;
    const int warp = tid >> 5;
    const int lane = tid & 31;
    const int warp_m = (warp & 1) * 64;
    const int warp_n = (warp >> 1) * 32;
    const int r  = lane >> 2;
    const int c4 = lane & 3;

    if (yt < 16) {
        // ---------------- energy path (3xTF32 hi/lo, cp.async) -------------
        const int lt = yt;
        const int mt_ = blockIdx.x;
        if (mt_ > lt) return;
        const int l0 = lt * 128, m0 = mt_ * 128;
        const uint32_t sbase = smem_u32(sm);

        const float* qb = g_q + (size_t)b * D_ * L_;
        const float* kb = g_k + (size_t)b * D_ * L_;

        auto load_slab = [&](int s) {
            const int kc = s * 32;
            const uint32_t qoff = sbase + (uint32_t)(s & 1) * EN_STAGE_F * 4u;
            const uint32_t koff = qoff + 4352u * 4u;
            #pragma unroll
            for (int i = 0; i < 4; i++) {
                const int f  = tid + i * 256;
                const int d  = f >> 5;
                const int l4 = f & 31;
                const uint32_t so = ((uint32_t)d * 136u + l4 * 4u) * 4u;
                cp_async16(qoff + so, qb + (size_t)(kc + d) * L_ + l0 + l4 * 4);
                cp_async16(koff + so, kb + (size_t)(kc + d) * L_ + m0 + l4 * 4);
            }
            CP_COMMIT();
        };

        float acc[4][4][4] = {};

        load_slab(0);
        load_slab(1);

        #pragma unroll
        for (int s = 0; s < 2; s++) {
            if (s == 0) CP_WAIT1(); else CP_WAIT0();
            __syncthreads();

            const float* Qs = sm + (s & 1) * EN_STAGE_F;
            const float* Ks = Qs + 4352;

            #pragma unroll
            for (int ks = 0; ks < 4; ks++) {
                const int k8 = ks * 8;
                uint32_t bfh[4][2], bfl[4][2];
                #pragma unroll
                for (int nt = 0; nt < 4; nt++) {
                    const int bn = warp_n + nt * 8 + r;
                    const float w0 = Ks[(k8 + c4    ) * 136 + bn];
                    const float w1 = Ks[(k8 + c4 + 4) * 136 + bn];
                    bfh[nt][0] = f2tf32(w0); bfl[nt][0] = f2tf32(w0 - __uint_as_float(bfh[nt][0]));
                    bfh[nt][1] = f2tf32(w1); bfl[nt][1] = f2tf32(w1 - __uint_as_float(bfh[nt][1]));
                }
                #pragma unroll
                for (int mt = 0; mt < 4; mt++) {
                    const int al_ = warp_m + mt * 16 + r;
                    const float v0 = Qs[(k8 + c4    ) * 136 + al_];
                    const float v1 = Qs[(k8 + c4    ) * 136 + al_ + 8];
                    const float v2 = Qs[(k8 + c4 + 4) * 136 + al_];
                    const float v3 = Qs[(k8 + c4 + 4) * 136 + al_ + 8];
                    uint32_t afh[4], afl[4];
                    afh[0] = f2tf32(v0); afl[0] = f2tf32(v0 - __uint_as_float(afh[0]));
                    afh[1] = f2tf32(v1); afl[1] = f2tf32(v1 - __uint_as_float(afh[1]));
                    afh[2] = f2tf32(v2); afl[2] = f2tf32(v2 - __uint_as_float(afh[2]));
                    afh[3] = f2tf32(v3); afl[3] = f2tf32(v3 - __uint_as_float(afh[3]));
                    #pragma unroll
                    for (int nt = 0; nt < 4; nt++) {
                        MMA_TF32(acc[mt][nt], afh, bfh[nt]);
                        MMA_TF32(acc[mt][nt], afh, bfl[nt]);
                        MMA_TF32(acc[mt][nt], afl, bfh[nt]);
                    }
                }
            }
            __syncthreads();
        }

        float* ab = att + (size_t)b * L_ * L_;
        #pragma unroll
        for (int mt = 0; mt < 4; mt++) {
            #pragma unroll
            for (int half = 0; half < 2; half++) {
                const int l = l0 + warp_m + mt * 16 + r + half * 8;
                #pragma unroll
                for (int nt = 0; nt < 4; nt++) {
                    const int m = m0 + warp_n + nt * 8 + c4 * 2;
                    float2 o;
                    o.x = acc[mt][nt][half*2 + 0];
                    o.y = acc[mt][nt][half*2 + 1];
                    *(float2*)(ab + (size_t)l * L_ + m) = o;
                }
            }
        }
    } else {
        // ---------------- v-projection path (plain tf32 -> fp16 out) -------
        const int r0 = (yt - 16) * 128;
        const int l0 = blockIdx.x * 128;
        const uint32_t sbase = smem_u32(sm);
        const float* xb = x + (size_t)b * C_ * L_;

        const int rowL = tid >> 3;
        const int q8   = tid & 7;

        float acc[4][4][4] = {};

        auto load_slab = [&](int s) {
            const int st = s & 1;
            const int kc = s * 32;
            const uint32_t aoff = sbase + (uint32_t)(st * QKV_STAGE_F) * 4u;
            const uint32_t boff = aoff + 4608u * 4u;
            #pragma unroll
            for (int i = 0; i < 4; i++) {
                const int rr = rowL + i * 32;
                cp_async16(aoff + ((uint32_t)rr * 36u + q8 * 4u) * 4u,
                           Wv + (size_t)(r0 + rr) * C_ + kc + q8 * 4);
                const int d  = (tid + i * 256) >> 5;
                const int l4 = (tid + i * 256) & 31;
                cp_async16(boff + ((uint32_t)d * 136u + l4 * 4u) * 4u,
                           xb + (size_t)(kc + d) * L_ + l0 + l4 * 4);
            }
            CP_COMMIT();
        };

        const int nst = C_ / 32;
        load_slab(0);

        for (int s = 0; s < nst; s++) {
            if (s + 1 < nst) { load_slab(s + 1); CP_WAIT1(); }
            else             { CP_WAIT0(); }
            __syncthreads();

            const float* As = sm + (s & 1) * QKV_STAGE_F;
            const float* Bs = As + 4608;

            #pragma unroll
            for (int ks = 0; ks < 4; ks++) {
                const int k8 = ks * 8;
                uint32_t af[4][4], bf[4][2];
                #pragma unroll
                for (int mt = 0; mt < 4; mt++) {
                    const int ar = warp_m + mt * 16 + r;
                    af[mt][0] = f2tf32(As[(ar    ) * 36 + k8 + c4]);
                    af[mt][1] = f2tf32(As[(ar + 8) * 36 + k8 + c4]);
                    af[mt][2] = f2tf32(As[(ar    ) * 36 + k8 + c4 + 4]);
                    af[mt][3] = f2tf32(As[(ar + 8) * 36 + k8 + c4 + 4]);
                }
                #pragma unroll
                for (int nt = 0; nt < 4; nt++) {
                    const int bn = warp_n + nt * 8 + r;
                    bf[nt][0] = f2tf32(Bs[(k8 + c4    ) * 136 + bn]);
                    bf[nt][1] = f2tf32(Bs[(k8 + c4 + 4) * 136 + bn]);
                }
                #pragma unroll
                for (int mt = 0; mt < 4; mt++)
                    #pragma unroll
                    for (int nt = 0; nt < 4; nt++)
                        MMA_TF32(acc[mt][nt], af[mt], bf[nt]);
            }
            __syncthreads();
        }

        #pragma unroll
        for (int mt = 0; mt < 4; mt++) {
            #pragma unroll
            for (int half = 0; half < 2; half++) {
                const int rr = r0 + warp_m + mt * 16 + r + half * 8;
                const float bias = bv[rr];
                __half* dst = g_v16 + ((size_t)b * C_ + rr) * L_;
                #pragma unroll
                for (int nt = 0; nt < 4; nt++) {
                    const int col = l0 + warp_n + nt * 8 + c4 * 2;
                    __half2 o = __floats2half2_rn(acc[mt][nt][half*2 + 0] + bias,
                                                  acc[mt][nt][half*2 + 1] + bias);
                    *(__half2*)(dst + col) = o;
                }
            }
        }
    }
}

// ===========================================================================
// Kernel 3: softmax, heavy rows first; f32 att full row + fp16 copy bounded
// to ceil(n/128)*128 (only region out_gemm's causal tiles ever read).
// ===========================================================================
__device__ __forceinline__ float block_reduce8(float v, float* red, bool is_max)
{
    #pragma unroll
    for (int o = 16; o > 0; o >>= 1) {
        const float t = __shfl_xor_sync(0xffffffffu, v, o);
        v = is_max ? fmaxf(v, t) : (v + t);
    }
    const int w = threadIdx.x >> 5;
    if ((threadIdx.x & 31) == 0) red[w] = v;
    __syncthreads();
    if (threadIdx.x < 32) {
        float t = (threadIdx.x < 8) ? red[threadIdx.x] : (is_max ? -INFINITY : 0.0f);
        #pragma unroll
        for (int o = 4; o > 0; o >>= 1) {
            const float u = __shfl_xor_sync(0xffffffffu, t, o);
            t = is_max ? fmaxf(t, u) : (t + u);
        }
        if (threadIdx.x == 0) red[0] = t;
    }
    __syncthreads();
    const float r = red[0];
    __syncthreads();
    return r;
}

__global__ __launch_bounds__(256) void softmax_kernel(
    float* __restrict__ att, const unsigned char* __restrict__ dmask)
{
    const int l = (L_ - 1) - blockIdx.x;   // heavy rows first
    const int b = blockIdx.y;
    const int tid = threadIdx.x;

    __shared__ float red[8];

    float*  arow = att + ((size_t)b * L_ + l) * L_;
    __half* hrow = g_a16 + ((size_t)b * L_ + l) * L_;
    const uchar4* mrow = (const uchar4*)(dmask + ((size_t)b * L_ + l) * L_);
    const int n = l + 1;
    const int nceil = (n + 127) & ~127;    // fp16 mirror needed only this far

    float v[8];
    float lmax = -INFINITY;
    #pragma unroll
    for (int it = 0; it < 2; it++) {
        const int j = tid + it * 256;
        const int base = j * 4;
        if (base < n) {
            float4 e4 = ((const float4*)arow)[j];
            uchar4 m4 = mrow[j];
            v[it*4+0] = (!m4.x)               ? e4.x : -INFINITY;
            v[it*4+1] = (base+1 < n && !m4.y) ? e4.y : -INFINITY;
            v[it*4+2] = (base+2 < n && !m4.z) ? e4.z : -INFINITY;
            v[it*4+3] = (base+3 < n && !m4.w) ? e4.w : -INFINITY;
            #pragma unroll
            for (int c = 0; c < 4; c++) lmax = fmaxf(lmax, v[it*4+c]);
        } else {
            v[it*4+0] = v[it*4+1] = v[it*4+2] = v[it*4+3] = -INFINITY;
        }
    }
    const float rmax = block_reduce8(lmax, red, true);

    float lsum = 0.0f;
    #pragma unroll
    for (int c = 0; c < 8; c++) {
        const float p = (v[c] == -INFINITY) ? 0.0f : __expf(v[c] - rmax);
        v[c] = p;
        lsum += p;
    }
    const float rsum = block_reduce8(lsum, red, false);
    const float inv = 1.0f / rsum;

    #pragma unroll
    for (int it = 0; it < 2; it++) {
        const int j = tid + it * 256;
        float4 o;
        o.x = v[it*4+0] * inv; o.y = v[it*4+1] * inv;
        o.z = v[it*4+2] * inv; o.w = v[it*4+3] * inv;
        ((float4*)arow)[j] = o;
        if (j * 4 < nceil) {
            __half2 h0 = __floats2half2_rn(o.x, o.y);
            __half2 h1 = __floats2half2_rn(o.z, o.w);
            uint2 hh;
            hh.x = *(uint32_t*)&h0;
            hh.y = *(uint32_t*)&h1;
            *(uint2*)(hrow + j * 4) = hh;
        }
    }
}

// ===========================================================================
// Kernel 4: out_gemm, fp16 mma.m16n8k16, BK=64, 3-stage cp.async,
// SINGLE sync per iteration (next-stage load issued AFTER the sync),
// ldmatrix.x4 fragments. Row stride 72 halves (144 B) -> banks 4r mod 32,
// conflict-free. Heavy tiles first; causal nst truncation.
// ===========================================================================
#define OG_ROWH 72                          // halves per row (64 + 8 pad)
#define OG_OPER_H (128 * OG_ROWH)           // 9216 halves per operand
#define OG_STAGE_H (2 * OG_OPER_H)          // 18432 halves per stage
#define OG_NSTAGE 3
#define OG_SMEM_BYTES (OG_NSTAGE * OG_STAGE_H * 2)   // 110592

__global__ __launch_bounds__(256, 2) void out_gemm_mma_kernel(
    float* __restrict__ out)
{
    extern __shared__ __align__(16) __half smh[];

    const int b  = blockIdx.z;
    const int m0 = ((int)gridDim.x - 1 - (int)blockIdx.x) * 128;  // heavy first
    const int c0 = blockIdx.y * 128;
    const int tid  = threadIdx.x;
    const int warp = tid >> 5;
    const int lane = tid & 31;
    const int warp_m = (warp & 1) * 64;
    const int warp_n = (warp >> 1) * 32;
    const int r  = lane >> 2;
    const int c4 = lane & 3;
    const uint32_t sbase = smem_u32(smh);

    const __half* vb = g_v16 + (size_t)b * C_ * L_;
    const __half* ab = g_a16 + (size_t)b * L_ * L_;

    // ldmatrix per-lane byte offsets within a stage
    const uint32_t aoffL = (uint32_t)(warp_m + (lane & 15)) * (OG_ROWH * 2u)
                         + (uint32_t)((lane >> 4) & 1) * 16u;
    const uint32_t boffL = (uint32_t)OG_OPER_H * 2u
                         + (uint32_t)(warp_n + ((lane >> 4) & 1) * 8 + (lane & 7)) * (OG_ROWH * 2u)
                         + (uint32_t)((lane >> 3) & 1) * 16u;

    float acc[4][4][4] = {};

    auto load_slab = [&](int s) {
        const int st = s % OG_NSTAGE;
        const int lc = s * 64;
        const uint32_t aoff = sbase + (uint32_t)(st * OG_STAGE_H) * 2u;
        const uint32_t boff = aoff + (uint32_t)OG_OPER_H * 2u;
        #pragma unroll
        for (int i = 0; i < 4; i++) {
            const int f  = tid + i * 256;
            const int rr = f >> 3;          // 0..127
            const int qq = f & 7;           // 16B chunk (8 halves) of 64
            const uint32_t so = (uint32_t)rr * (OG_ROWH * 2u) + (uint32_t)qq * 16u;
            cp_async16(aoff + so, vb + (size_t)(c0 + rr) * L_ + lc + qq * 8);
            cp_async16(boff + so, ab + (size_t)(m0 + rr) * L_ + lc + qq * 8);
        }
        CP_COMMIT();
    };

    const int nst = (m0 + 128) / 64;        // >= 2
    load_slab(0);
    if (nst > 1) load_slab(1);

    for (int s = 0; s < nst; s++) {
        if (s + 1 < nst) CP_WAIT1(); else CP_WAIT0();
        __syncthreads();
        if (s + 2 < nst) load_slab(s + 2);   // after sync: target buffer free

        const uint32_t stb = sbase + (uint32_t)((s % OG_NSTAGE) * OG_STAGE_H) * 2u;
        const uint32_t aAddr = stb + aoffL;
        const uint32_t bAddr = stb + boffL;

        #pragma unroll
        for (int ks = 0; ks < 4; ks++) {
            const uint32_t kb = (uint32_t)ks * 32u;   // k16 step = 32 bytes
            uint32_t af[4][4], bf[4][2];
            #pragma unroll
            for (int mt = 0; mt < 4; mt++)
                LDSM_X4(af[mt][0], af[mt][1], af[mt][2], af[mt][3],
                        aAddr + (uint32_t)mt * (16u * OG_ROWH * 2u) + kb);
            #pragma unroll
            for (int g = 0; g < 2; g++)
                LDSM_X4(bf[2*g][0], bf[2*g][1], bf[2*g+1][0], bf[2*g+1][1],
                        bAddr + (uint32_t)g * (16u * OG_ROWH * 2u) + kb);
            #pragma unroll
            for (int mt = 0; mt < 4; mt++)
                #pragma unroll
                for (int nt = 0; nt < 4; nt++)
                    MMA_F16(acc[mt][nt], af[mt], bf[nt]);
        }
    }

    float* ob = out + (size_t)b * C_ * L_;
    #pragma unroll
    for (int mt = 0; mt < 4; mt++) {
        const int crow = c0 + warp_m + mt * 16 + r;
        #pragma unroll
        for (int nt = 0; nt < 4; nt++) {
            const int mcol = m0 + warp_n + nt * 8 + c4 * 2;
            float2 o0 = make_float2(acc[mt][nt][0], acc[mt][nt][1]);
            float2 o1 = make_float2(acc[mt][nt][2], acc[mt][nt][3]);
            *(float2*)(ob + (size_t)crow       * L_ + mcol) = o0;
            *(float2*)(ob + (size_t)(crow + 8) * L_ + mcol) = o1;
        }
    }
}

// ===========================================================================
extern "C" void kernel_launch(void* const* d_in, const int* in_sizes, int n_in,
                              void* d_out, int out_size)
{
    (void)in_sizes; (void)n_in; (void)out_size;
    const float* x          = (const float*)d_in[0];
    const unsigned char* dm = (const unsigned char*)d_in[1];
    const float* Wq = (const float*)d_in[2];
    const float* bq = (const float*)d_in[3];
    const float* Wk = (const float*)d_in[4];
    const float* bk = (const float*)d_in[5];
    const float* Wv = (const float*)d_in[6];
    const float* bv = (const float*)d_in[7];

    float* out = (float*)d_out;                      // (B, C, L)
    float* att = out + (size_t)B_ * C_ * L_;         // (B, L, L)

    cudaFuncSetAttribute(qk_proj_mma_kernel,
                         cudaFuncAttributeMaxDynamicSharedMemorySize, QK_SMEM_BYTES);
    cudaFuncSetAttribute(energy_v_fused_kernel,
                         cudaFuncAttributeMaxDynamicSharedMemorySize, EV_SMEM_BYTES);
    cudaFuncSetAttribute(out_gemm_mma_kernel,
                         cudaFuncAttributeMaxDynamicSharedMemorySize, OG_SMEM_BYTES);

    qk_proj_mma_kernel<<<dim3(L_/64, 1, B_), 256, QK_SMEM_BYTES>>>(x, Wq, bq, Wk, bk);
    energy_v_fused_kernel<<<dim3(16, 20, B_), 256, EV_SMEM_BYTES>>>(att, x, Wv, bv);
    softmax_kernel     <<<dim3(L_, B_), 256>>>(att, dm);
    out_gemm_mma_kernel<<<dim3(L_/128, C_/128, B_), 256, OG_SMEM_BYTES>>>(out);
}

// round 15
// speedup vs baseline: 1.0487x; 1.0487x over previous
#include <cuda_runtime.h>
#include <cuda_fp16.h>
#include <math.h>
#include <stdint.h>

#define B_ 8
#define C_ 512
#define L_ 2048
#define D_ 64

// Scratch (allocation-free rule: device globals)
__device__ float  g_q[B_*D_*L_];                 // (b, d, l)
__device__ float  g_k[B_*D_*L_];                 // (b, d, l)
__device__ __half g_v16[(size_t)B_*C_*L_];       // (b, c, l) fp16
__device__ __half g_a16[(size_t)B_*L_*L_];       // (b, m, l) fp16 attention copy

__device__ __forceinline__ uint32_t f2tf32(float f) {
    uint32_t u;
    asm("cvt.rna.tf32.f32 %0, %1;" : "=r"(u) : "f"(f));
    return u;
}
__device__ __forceinline__ uint32_t smem_u32(const void* p) {
    uint32_t a;
    asm("{ .reg .u64 t; cvta.to.shared.u64 t, %1; cvt.u32.u64 %0, t; }"
        : "=r"(a) : "l"(p));
    return a;
}
__device__ __forceinline__ void cp_async16(uint32_t dst, const void* src) {
    asm volatile("cp.async.ca.shared.global [%0], [%1], 16;"
                 :: "r"(dst), "l"(src));
}
#define CP_COMMIT() asm volatile("cp.async.commit_group;" ::: "memory")
#define CP_WAIT1()  asm volatile("cp.async.wait_group 1;" ::: "memory")
#define CP_WAIT0()  asm volatile("cp.async.wait_group 0;" ::: "memory")

#define MMA_TF32(acc, af, bf)                                                  \
    asm volatile(                                                              \
        "mma.sync.aligned.m16n8k8.row.col.f32.tf32.tf32.f32 "                  \
        "{%0,%1,%2,%3}, {%4,%5,%6,%7}, {%8,%9}, {%0,%1,%2,%3};"                \
        : "+f"((acc)[0]), "+f"((acc)[1]), "+f"((acc)[2]), "+f"((acc)[3])       \
        : "r"((af)[0]), "r"((af)[1]), "r"((af)[2]), "r"((af)[3]),              \
          "r"((bf)[0]), "r"((bf)[1]))

#define MMA_F16(acc, af, bf)                                                   \
    asm volatile(                                                              \
        "mma.sync.aligned.m16n8k16.row.col.f32.f16.f16.f32 "                   \
        "{%0,%1,%2,%3}, {%4,%5,%6,%7}, {%8,%9}, {%0,%1,%2,%3};"                \
        : "+f"((acc)[0]), "+f"((acc)[1]), "+f"((acc)[2]), "+f"((acc)[3])       \
        : "r"((af)[0]), "r"((af)[1]), "r"((af)[2]), "r"((af)[3]),              \
          "r"((bf)[0]), "r"((bf)[1]))

#define LDSM_X4(r0, r1, r2, r3, addr)                                          \
    asm volatile("ldmatrix.sync.aligned.m8n8.x4.shared.b16 {%0,%1,%2,%3}, [%4];" \
                 : "=r"(r0), "=r"(r1), "=r"(r2), "=r"(r3) : "r"(addr))

// ===========================================================================
// Kernel 1: q/k projection, 3xTF32 hi/lo, 64-wide l tiles (proven R9).
// ===========================================================================
#define QK_STAGE_F 6912
#define QK_SMEM_BYTES (2 * QK_STAGE_F * 4)   // 55296

__global__ __launch_bounds__(256, 2) void qk_proj_mma_kernel(
    const float* __restrict__ x,
    const float* __restrict__ Wq, const float* __restrict__ bq,
    const float* __restrict__ Wk, const float* __restrict__ bk)
{
    extern __shared__ __align__(16) float sm[];

    const int b  = blockIdx.z;
    const int l0 = blockIdx.x * 64;
    const int tid  = threadIdx.x;
    const int warp = tid >> 5;
    const int lane = tid & 31;
    const int warp_m = (warp & 3) * 32;
    const int warp_n = (warp >> 2) * 32;
    const int r  = lane >> 2;
    const int c4 = lane & 3;
    const uint32_t sbase = smem_u32(sm);

    const float* xb = x + (size_t)b * C_ * L_;

    const int rowL = tid >> 3;            // 0..31
    const int q8   = tid & 7;

    float acc[2][4][4] = {};

    auto load_slab = [&](int s) {
        const int st = s & 1;
        const int kc = s * 32;
        const uint32_t aoff = sbase + (uint32_t)(st * QK_STAGE_F) * 4u;
        const uint32_t boff = aoff + 4608u * 4u;
        #pragma unroll
        for (int i = 0; i < 4; i++) {
            const int rr = rowL + i * 32;
            const float* wp = (rr < 64) ? Wq + (size_t)rr * C_
                                        : Wk + (size_t)(rr - 64) * C_;
            cp_async16(aoff + ((uint32_t)rr * 36u + q8 * 4u) * 4u, wp + kc + q8 * 4);
        }
        #pragma unroll
        for (int i = 0; i < 2; i++) {
            const int f  = tid + i * 256;
            const int d  = f >> 4;        // 0..31
            const int l4 = f & 15;
            cp_async16(boff + ((uint32_t)d * 72u + l4 * 4u) * 4u,
                       xb + (size_t)(kc + d) * L_ + l0 + l4 * 4);
        }
        CP_COMMIT();
    };

    const int nst = C_ / 32;   // 16
    load_slab(0);

    for (int s = 0; s < nst; s++) {
        if (s + 1 < nst) { load_slab(s + 1); CP_WAIT1(); }
        else             { CP_WAIT0(); }
        __syncthreads();

        const float* As = sm + (s & 1) * QK_STAGE_F;
        const float* Bs = As + 4608;

        #pragma unroll
        for (int ks = 0; ks < 4; ks++) {
            const int k8 = ks * 8;
            uint32_t afh[2][4], afl[2][4], bfh[4][2], bfl[4][2];
            #pragma unroll
            for (int mt = 0; mt < 2; mt++) {
                const int ar = warp_m + mt * 16 + r;
                const float v0 = As[(ar    ) * 36 + k8 + c4];
                const float v1 = As[(ar + 8) * 36 + k8 + c4];
                const float v2 = As[(ar    ) * 36 + k8 + c4 + 4];
                const float v3 = As[(ar + 8) * 36 + k8 + c4 + 4];
                afh[mt][0] = f2tf32(v0); afl[mt][0] = f2tf32(v0 - __uint_as_float(afh[mt][0]));
                afh[mt][1] = f2tf32(v1); afl[mt][1] = f2tf32(v1 - __uint_as_float(afh[mt][1]));
                afh[mt][2] = f2tf32(v2); afl[mt][2] = f2tf32(v2 - __uint_as_float(afh[mt][2]));
                afh[mt][3] = f2tf32(v3); afl[mt][3] = f2tf32(v3 - __uint_as_float(afh[mt][3]));
            }
            #pragma unroll
            for (int nt = 0; nt < 4; nt++) {
                const int bn = warp_n + nt * 8 + r;
                const float w0 = Bs[(k8 + c4    ) * 72 + bn];
                const float w1 = Bs[(k8 + c4 + 4) * 72 + bn];
                bfh[nt][0] = f2tf32(w0); bfl[nt][0] = f2tf32(w0 - __uint_as_float(bfh[nt][0]));
                bfh[nt][1] = f2tf32(w1); bfl[nt][1] = f2tf32(w1 - __uint_as_float(bfh[nt][1]));
            }
            #pragma unroll
            for (int mt = 0; mt < 2; mt++)
                #pragma unroll
                for (int nt = 0; nt < 4; nt++) {
                    MMA_TF32(acc[mt][nt], afh[mt], bfh[nt]);
                    MMA_TF32(acc[mt][nt], afh[mt], bfl[nt]);
                    MMA_TF32(acc[mt][nt], afl[mt], bfh[nt]);
                }
        }
        __syncthreads();
    }

    #pragma unroll
    for (int mt = 0; mt < 2; mt++) {
        #pragma unroll
        for (int half = 0; half < 2; half++) {
            const int rr = warp_m + mt * 16 + r + half * 8;
            float bias; float* dst;
            if (rr < 64) { bias = bq[rr];    dst = g_q + ((size_t)b*D_ + rr)      * L_; }
            else         { bias = bk[rr-64]; dst = g_k + ((size_t)b*D_ + (rr-64)) * L_; }
            #pragma unroll
            for (int nt = 0; nt < 4; nt++) {
                const int col = l0 + warp_n + nt * 8 + c4 * 2;
                float2 o;
                o.x = acc[mt][nt][half*2 + 0] + bias;
                o.y = acc[mt][nt][half*2 + 1] + bias;
                *(float2*)(dst + col) = o;
            }
        }
    }
}

// ===========================================================================
// Kernel 2: FUSED energy + v-projection (proven R11).
// ===========================================================================
#define EN_STAGE_F 8704
#define QKV_STAGE_F 8960
#define EV_SMEM_BYTES (2 * QKV_STAGE_F * 4)   // 71680

__global__ __launch_bounds__(256, 2) void energy_v_fused_kernel(
    float* __restrict__ att,
    const float* __restrict__ x,
    const float* __restrict__ Wv, const float* __restrict__ bv)
{
    extern __shared__ __align__(16) float sm[];

    const int b   = blockIdx.z;
    const int yt  = blockIdx.y;
    const int tid = threadIdx.x;
    const int warp = tid >> 5;
    const int lane = tid & 31;
    const int warp_m = (warp & 1) * 64;
    const int warp_n = (warp >> 1) * 32;
    const int r  = lane >> 2;
    const int c4 = lane & 3;

    if (yt < 16) {
        // ---------------- energy path (3xTF32 hi/lo, cp.async) -------------
        const int lt = yt;
        const int mt_ = blockIdx.x;
        if (mt_ > lt) return;
        const int l0 = lt * 128, m0 = mt_ * 128;
        const uint32_t sbase = smem_u32(sm);

        const float* qb = g_q + (size_t)b * D_ * L_;
        const float* kb = g_k + (size_t)b * D_ * L_;

        auto load_slab = [&](int s) {
            const int kc = s * 32;
            const uint32_t qoff = sbase + (uint32_t)(s & 1) * EN_STAGE_F * 4u;
            const uint32_t koff = qoff + 4352u * 4u;
            #pragma unroll
            for (int i = 0; i < 4; i++) {
                const int f  = tid + i * 256;
                const int d  = f >> 5;
                const int l4 = f & 31;
                const uint32_t so = ((uint32_t)d * 136u + l4 * 4u) * 4u;
                cp_async16(qoff + so, qb + (size_t)(kc + d) * L_ + l0 + l4 * 4);
                cp_async16(koff + so, kb + (size_t)(kc + d) * L_ + m0 + l4 * 4);
            }
            CP_COMMIT();
        };

        float acc[4][4][4] = {};

        load_slab(0);
        load_slab(1);

        #pragma unroll
        for (int s = 0; s < 2; s++) {
            if (s == 0) CP_WAIT1(); else CP_WAIT0();
            __syncthreads();

            const float* Qs = sm + (s & 1) * EN_STAGE_F;
            const float* Ks = Qs + 4352;

            #pragma unroll
            for (int ks = 0; ks < 4; ks++) {
                const int k8 = ks * 8;
                uint32_t bfh[4][2], bfl[4][2];
                #pragma unroll
                for (int nt = 0; nt < 4; nt++) {
                    const int bn = warp_n + nt * 8 + r;
                    const float w0 = Ks[(k8 + c4    ) * 136 + bn];
                    const float w1 = Ks[(k8 + c4 + 4) * 136 + bn];
                    bfh[nt][0] = f2tf32(w0); bfl[nt][0] = f2tf32(w0 - __uint_as_float(bfh[nt][0]));
                    bfh[nt][1] = f2tf32(w1); bfl[nt][1] = f2tf32(w1 - __uint_as_float(bfh[nt][1]));
                }
                #pragma unroll
                for (int mt = 0; mt < 4; mt++) {
                    const int al_ = warp_m + mt * 16 + r;
                    const float v0 = Qs[(k8 + c4    ) * 136 + al_];
                    const float v1 = Qs[(k8 + c4    ) * 136 + al_ + 8];
                    const float v2 = Qs[(k8 + c4 + 4) * 136 + al_];
                    const float v3 = Qs[(k8 + c4 + 4) * 136 + al_ + 8];
                    uint32_t afh[4], afl[4];
                    afh[0] = f2tf32(v0); afl[0] = f2tf32(v0 - __uint_as_float(afh[0]));
                    afh[1] = f2tf32(v1); afl[1] = f2tf32(v1 - __uint_as_float(afh[1]));
                    afh[2] = f2tf32(v2); afl[2] = f2tf32(v2 - __uint_as_float(afh[2]));
                    afh[3] = f2tf32(v3); afl[3] = f2tf32(v3 - __uint_as_float(afh[3]));
                    #pragma unroll
                    for (int nt = 0; nt < 4; nt++) {
                        MMA_TF32(acc[mt][nt], afh, bfh[nt]);
                        MMA_TF32(acc[mt][nt], afh, bfl[nt]);
                        MMA_TF32(acc[mt][nt], afl, bfh[nt]);
                    }
                }
            }
            __syncthreads();
        }

        float* ab = att + (size_t)b * L_ * L_;
        #pragma unroll
        for (int mt = 0; mt < 4; mt++) {
            #pragma unroll
            for (int half = 0; half < 2; half++) {
                const int l = l0 + warp_m + mt * 16 + r + half * 8;
                #pragma unroll
                for (int nt = 0; nt < 4; nt++) {
                    const int m = m0 + warp_n + nt * 8 + c4 * 2;
                    float2 o;
                    o.x = acc[mt][nt][half*2 + 0];
                    o.y = acc[mt][nt][half*2 + 1];
                    *(float2*)(ab + (size_t)l * L_ + m) = o;
                }
            }
        }
    } else {
        // ---------------- v-projection path (plain tf32 -> fp16 out) -------
        const int r0 = (yt - 16) * 128;
        const int l0 = blockIdx.x * 128;
        const uint32_t sbase = smem_u32(sm);
        const float* xb = x + (size_t)b * C_ * L_;

        const int rowL = tid >> 3;
        const int q8   = tid & 7;

        float acc[4][4][4] = {};

        auto load_slab = [&](int s) {
            const int st = s & 1;
            const int kc = s * 32;
            const uint32_t aoff = sbase + (uint32_t)(st * QKV_STAGE_F) * 4u;
            const uint32_t boff = aoff + 4608u * 4u;
            #pragma unroll
            for (int i = 0; i < 4; i++) {
                const int rr = rowL + i * 32;
                cp_async16(aoff + ((uint32_t)rr * 36u + q8 * 4u) * 4u,
                           Wv + (size_t)(r0 + rr) * C_ + kc + q8 * 4);
                const int d  = (tid + i * 256) >> 5;
                const int l4 = (tid + i * 256) & 31;
                cp_async16(boff + ((uint32_t)d * 136u + l4 * 4u) * 4u,
                           xb + (size_t)(kc + d) * L_ + l0 + l4 * 4);
            }
            CP_COMMIT();
        };

        const int nst = C_ / 32;
        load_slab(0);

        for (int s = 0; s < nst; s++) {
            if (s + 1 < nst) { load_slab(s + 1); CP_WAIT1(); }
            else             { CP_WAIT0(); }
            __syncthreads();

            const float* As = sm + (s & 1) * QKV_STAGE_F;
            const float* Bs = As + 4608;

            #pragma unroll
            for (int ks = 0; ks < 4; ks++) {
                const int k8 = ks * 8;
                uint32_t af[4][4], bf[4][2];
                #pragma unroll
                for (int mt = 0; mt < 4; mt++) {
                    const int ar = warp_m + mt * 16 + r;
                    af[mt][0] = f2tf32(As[(ar    ) * 36 + k8 + c4]);
                    af[mt][1] = f2tf32(As[(ar + 8) * 36 + k8 + c4]);
                    af[mt][2] = f2tf32(As[(ar    ) * 36 + k8 + c4 + 4]);
                    af[mt][3] = f2tf32(As[(ar + 8) * 36 + k8 + c4 + 4]);
                }
                #pragma unroll
                for (int nt = 0; nt < 4; nt++) {
                    const int bn = warp_n + nt * 8 + r;
                    bf[nt][0] = f2tf32(Bs[(k8 + c4    ) * 136 + bn]);
                    bf[nt][1] = f2tf32(Bs[(k8 + c4 + 4) * 136 + bn]);
                }
                #pragma unroll
                for (int mt = 0; mt < 4; mt++)
                    #pragma unroll
                    for (int nt = 0; nt < 4; nt++)
                        MMA_TF32(acc[mt][nt], af[mt], bf[nt]);
            }
            __syncthreads();
        }

        #pragma unroll
        for (int mt = 0; mt < 4; mt++) {
            #pragma unroll
            for (int half = 0; half < 2; half++) {
                const int rr = r0 + warp_m + mt * 16 + r + half * 8;
                const float bias = bv[rr];
                __half* dst = g_v16 + ((size_t)b * C_ + rr) * L_;
                #pragma unroll
                for (int nt = 0; nt < 4; nt++) {
                    const int col = l0 + warp_n + nt * 8 + c4 * 2;
                    __half2 o = __floats2half2_rn(acc[mt][nt][half*2 + 0] + bias,
                                                  acc[mt][nt][half*2 + 1] + bias);
                    *(__half2*)(dst + col) = o;
                }
            }
        }
    }
}

// ===========================================================================
// Kernel 3: softmax, heavy rows first; f32 att full row + fp16 copy bounded
// to ceil(n/64)*64 (out_gemm now reads 64-wide m-tiles).
// ===========================================================================
__device__ __forceinline__ float block_reduce8(float v, float* red, bool is_max)
{
    #pragma unroll
    for (int o = 16; o > 0; o >>= 1) {
        const float t = __shfl_xor_sync(0xffffffffu, v, o);
        v = is_max ? fmaxf(v, t) : (v + t);
    }
    const int w = threadIdx.x >> 5;
    if ((threadIdx.x & 31) == 0) red[w] = v;
    __syncthreads();
    if (threadIdx.x < 32) {
        float t = (threadIdx.x < 8) ? red[threadIdx.x] : (is_max ? -INFINITY : 0.0f);
        #pragma unroll
        for (int o = 4; o > 0; o >>= 1) {
            const float u = __shfl_xor_sync(0xffffffffu, t, o);
            t = is_max ? fmaxf(t, u) : (t + u);
        }
        if (threadIdx.x == 0) red[0] = t;
    }
    __syncthreads();
    const float r = red[0];
    __syncthreads();
    return r;
}

__global__ __launch_bounds__(256) void softmax_kernel(
    float* __restrict__ att, const unsigned char* __restrict__ dmask)
{
    const int l = (L_ - 1) - blockIdx.x;   // heavy rows first
    const int b = blockIdx.y;
    const int tid = threadIdx.x;

    __shared__ float red[8];

    float*  arow = att + ((size_t)b * L_ + l) * L_;
    __half* hrow = g_a16 + ((size_t)b * L_ + l) * L_;
    const uchar4* mrow = (const uchar4*)(dmask + ((size_t)b * L_ + l) * L_);
    const int n = l + 1;
    const int nceil = (n + 63) & ~63;      // fp16 mirror needed only this far

    float v[8];
    float lmax = -INFINITY;
    #pragma unroll
    for (int it = 0; it < 2; it++) {
        const int j = tid + it * 256;
        const int base = j * 4;
        if (base < n) {
            float4 e4 = ((const float4*)arow)[j];
            uchar4 m4 = mrow[j];
            v[it*4+0] = (!m4.x)               ? e4.x : -INFINITY;
            v[it*4+1] = (base+1 < n && !m4.y) ? e4.y : -INFINITY;
            v[it*4+2] = (base+2 < n && !m4.z) ? e4.z : -INFINITY;
            v[it*4+3] = (base+3 < n && !m4.w) ? e4.w : -INFINITY;
            #pragma unroll
            for (int c = 0; c < 4; c++) lmax = fmaxf(lmax, v[it*4+c]);
        } else {
            v[it*4+0] = v[it*4+1] = v[it*4+2] = v[it*4+3] = -INFINITY;
        }
    }
    const float rmax = block_reduce8(lmax, red, true);

    float lsum = 0.0f;
    #pragma unroll
    for (int c = 0; c < 8; c++) {
        const float p = (v[c] == -INFINITY) ? 0.0f : __expf(v[c] - rmax);
        v[c] = p;
        lsum += p;
    }
    const float rsum = block_reduce8(lsum, red, false);
    const float inv = 1.0f / rsum;

    #pragma unroll
    for (int it = 0; it < 2; it++) {
        const int j = tid + it * 256;
        float4 o;
        o.x = v[it*4+0] * inv; o.y = v[it*4+1] * inv;
        o.z = v[it*4+2] * inv; o.w = v[it*4+3] * inv;
        ((float4*)arow)[j] = o;
        if (j * 4 < nceil) {
            __half2 h0 = __floats2half2_rn(o.x, o.y);
            __half2 h1 = __floats2half2_rn(o.z, o.w);
            uint2 hh;
            hh.x = *(uint32_t*)&h0;
            hh.y = *(uint32_t*)&h1;
            *(uint2*)(hrow + j * 4) = hh;
        }
    }
}

// ===========================================================================
// Kernel 4: out_gemm, fp16 mma.m16n8k16, 128(c) x 64(m) tile, 8 warps,
// BK=64, 2-stage cp.async, SINGLE sync/iter, ldmatrix.x4, 3 CTAs/SM.
// Warp layout: warp_m = (warp&1)*64 (c), warp_n = (warp>>1)*16 (m).
// acc[4][2][4] = 32 regs -> fits launch_bounds(256,3).
// Row stride 72 halves (144 B): ldsm banks 4r mod 32, conflict-free.
// Heavy tiles first; causal nst truncation (nst = m0/64 + 1).
// ===========================================================================
#define OG_ROWH 72
#define OG_A_H (128 * OG_ROWH)              // 9216 halves
#define OG_B_H (64 * OG_ROWH)               // 4608 halves
#define OG_STAGE_H (OG_A_H + OG_B_H)        // 13824 halves
#define OG_SMEM_BYTES (2 * OG_STAGE_H * 2)  // 55296

__global__ __launch_bounds__(256, 3) void out_gemm_mma_kernel(
    float* __restrict__ out)
{
    extern __shared__ __align__(16) __half smh[];

    const int b  = blockIdx.z;
    const int m0 = ((int)gridDim.x - 1 - (int)blockIdx.x) * 64;   // heavy first
    const int c0 = blockIdx.y * 128;
    const int tid  = threadIdx.x;
    const int warp = tid >> 5;
    const int lane = tid & 31;
    const int warp_m = (warp & 1) * 64;     // c offset
    const int warp_n = (warp >> 1) * 16;    // m offset
    const int r  = lane >> 2;
    const int c4 = lane & 3;
    const uint32_t sbase = smem_u32(smh);

    const __half* vb = g_v16 + (size_t)b * C_ * L_;
    const __half* ab = g_a16 + (size_t)b * L_ * L_;

    // ldmatrix per-lane byte offsets within a stage
    const uint32_t aoffL = (uint32_t)(warp_m + (lane & 15)) * (OG_ROWH * 2u)
                         + (uint32_t)((lane >> 4) & 1) * 16u;
    const uint32_t boffL = (uint32_t)OG_A_H * 2u
                         + (uint32_t)(warp_n + ((lane >> 4) & 1) * 8 + (lane & 7)) * (OG_ROWH * 2u)
                         + (uint32_t)((lane >> 3) & 1) * 16u;

    float acc[4][2][4] = {};

    auto load_slab = [&](int s) {
        const int st = s & 1;
        const int lc = s * 64;
        const uint32_t aoff = sbase + (uint32_t)(st * OG_STAGE_H) * 2u;
        const uint32_t boff = aoff + (uint32_t)OG_A_H * 2u;
        #pragma unroll
        for (int i = 0; i < 4; i++) {       // A: 128 rows x 64 halves
            const int f  = tid + i * 256;
            const int rr = f >> 3;
            const int qq = f & 7;
            cp_async16(aoff + (uint32_t)rr * (OG_ROWH * 2u) + (uint32_t)qq * 16u,
                       vb + (size_t)(c0 + rr) * L_ + lc + qq * 8);
        }
        #pragma unroll
        for (int i = 0; i < 2; i++) {       // B: 64 rows x 64 halves
            const int f  = tid + i * 256;
            const int rr = f >> 3;
            const int qq = f & 7;
            cp_async16(boff + (uint32_t)rr * (OG_ROWH * 2u) + (uint32_t)qq * 16u,
                       ab + (size_t)(m0 + rr) * L_ + lc + qq * 8);
        }
        CP_COMMIT();
    };

    const int nst = m0 / 64 + 1;            // causal: 1..32
    load_slab(0);

    for (int s = 0; s < nst; s++) {
        CP_WAIT0();
        __syncthreads();
        if (s + 1 < nst) load_slab(s + 1);  // after sync: target buffer free

        const uint32_t stb = sbase + (uint32_t)((s & 1) * OG_STAGE_H) * 2u;
        const uint32_t aAddr = stb + aoffL;
        const uint32_t bAddr = stb + boffL;

        #pragma unroll
        for (int ks = 0; ks < 4; ks++) {
            const uint32_t kb = (uint32_t)ks * 32u;   // k16 step = 32 bytes
            uint32_t af[4][4], bf[2][2];
            #pragma unroll
            for (int mt = 0; mt < 4; mt++)
                LDSM_X4(af[mt][0], af[mt][1], af[mt][2], af[mt][3],
                        aAddr + (uint32_t)mt * (16u * OG_ROWH * 2u) + kb);
            LDSM_X4(bf[0][0], bf[0][1], bf[1][0], bf[1][1], bAddr + kb);
            #pragma unroll
            for (int mt = 0; mt < 4; mt++)
                #pragma unroll
                for (int nt = 0; nt < 2; nt++)
                    MMA_F16(acc[mt][nt], af[mt], bf[nt]);
        }
    }

    float* ob = out + (size_t)b * C_ * L_;
    #pragma unroll
    for (int mt = 0; mt < 4; mt++) {
        const int crow = c0 + warp_m + mt * 16 + r;
        #pragma unroll
        for (int nt = 0; nt < 2; nt++) {
            const int mcol = m0 + warp_n + nt * 8 + c4 * 2;
            float2 o0 = make_float2(acc[mt][nt][0], acc[mt][nt][1]);
            float2 o1 = make_float2(acc[mt][nt][2], acc[mt][nt][3]);
            *(float2*)(ob + (size_t)crow       * L_ + mcol) = o0;
            *(float2*)(ob + (size_t)(crow + 8) * L_ + mcol) = o1;
        }
    }
}

// ===========================================================================
extern "C" void kernel_launch(void* const* d_in, const int* in_sizes, int n_in,
                              void* d_out, int out_size)
{
    (void)in_sizes; (void)n_in; (void)out_size;
    const float* x          = (const float*)d_in[0];
    const unsigned char* dm = (const unsigned char*)d_in[1];
    const float* Wq = (const float*)d_in[2];
    const float* bq = (const float*)d_in[3];
    const float* Wk = (const float*)d_in[4];
    const float* bk = (const float*)d_in[5];
    const float* Wv = (const float*)d_in[6];
    const float* bv = (const float*)d_in[7];

    float* out = (float*)d_out;                      // (B, C, L)
    float* att = out + (size_t)B_ * C_ * L_;         // (B, L, L)

    cudaFuncSetAttribute(qk_proj_mma_kernel,
                         cudaFuncAttributeMaxDynamicSharedMemorySize, QK_SMEM_BYTES);
    cudaFuncSetAttribute(energy_v_fused_kernel,
                         cudaFuncAttributeMaxDynamicSharedMemorySize, EV_SMEM_BYTES);
    cudaFuncSetAttribute(out_gemm_mma_kernel,
                         cudaFuncAttributeMaxDynamicSharedMemorySize, OG_SMEM_BYTES);

    qk_proj_mma_kernel<<<dim3(L_/64, 1, B_), 256, QK_SMEM_BYTES>>>(x, Wq, bq, Wk, bk);
    energy_v_fused_kernel<<<dim3(16, 20, B_), 256, EV_SMEM_BYTES>>>(att, x, Wv, bv);
    softmax_kernel     <<<dim3(L_, B_), 256>>>(att, dm);
    out_gemm_mma_kernel<<<dim3(L_/64, C_/128, B_), 256, OG_SMEM_BYTES>>>(out);
}